// round 1
// baseline (speedup 1.0000x reference)
#include <cuda_runtime.h>

#define Dd 64
#define Hh 128
#define Ww 128
#define HW (Hh*Ww)
#define NN (Dd*Hh*Ww)

// ---------------- scratch (device globals: alloc-free, capture-safe) ----------
__device__ float g_t[NN];
__device__ float g_z[NN];
__device__ float g_p[NN];
__device__ float g_q[NN];
__device__ float g_s[NN];
__device__ float g_zp[NN];
__device__ float g_sums[HW];
__device__ float g_h1[16*NN];
__device__ float g_h2[16*NN];

// ---------------- packed f32x2 helpers (FFMA2: 2 FMAs per issue slot) ---------
static __device__ __forceinline__ unsigned long long pack2(float lo, float hi){
    unsigned long long r;
    asm("mov.b64 %0, {%1,%2};" : "=l"(r) : "f"(lo), "f"(hi));
    return r;
}
static __device__ __forceinline__ void unpack2(unsigned long long v, float &lo, float &hi){
    asm("mov.b64 {%0,%1}, %2;" : "=f"(lo), "=f"(hi) : "l"(v));
}
static __device__ __forceinline__ void ffma2(unsigned long long &d, unsigned long long a, unsigned long long b){
    asm("fma.rn.f32x2 %0, %1, %2, %0;" : "+l"(d) : "l"(a), "l"(b));
}

// x = fdiff(z, axis) evaluated on the fly (0:W, 1:H, 2:D, 3:identity),
// zero outside the volume (conv SAME padding) and at the fdiff tail.
template<int MODE>
static __device__ __forceinline__ float getx(int d, int h, int w){
    if (d < 0 || d >= Dd || h < 0 || h >= Hh || w < 0 || w >= Ww) return 0.f;
    int idx = (d*Hh + h)*Ww + w;
    if (MODE == 0) return (w < Ww-1) ? g_z[idx+1]  - g_z[idx] : 0.f;
    if (MODE == 1) return (h < Hh-1) ? g_z[idx+Ww] - g_z[idx] : 0.f;
    if (MODE == 2) return (d < Dd-1) ? g_z[idx+HW] - g_z[idx] : 0.f;
    return g_z[idx];
}

// ---------------- init: t = image, outs[0] = image, p=q=s=0 -------------------
__global__ void k_init(const float* __restrict__ img, float* __restrict__ outp){
    int idx = blockIdx.x*256 + threadIdx.x;
    float v = img[idx];
    g_t[idx] = v;
    outp[idx] = v;
    g_p[idx] = 0.f; g_q[idx] = 0.f; g_s[idx] = 0.f;
}

// ---------------- column sum over D ------------------------------------------
__global__ void k_colsum(){
    int j = blockIdx.x*256 + threadIdx.x;     // 0..HW-1
    float a0=0.f, a1=0.f, a2=0.f, a3=0.f;
    #pragma unroll
    for (int d = 0; d < Dd; d += 4){
        a0 += g_t[(d+0)*HW + j];
        a1 += g_t[(d+1)*HW + j];
        a2 += g_t[(d+2)*HW + j];
        a3 += g_t[(d+3)*HW + j];
    }
    g_sums[j] = (a0+a1)+(a2+a3);
}

// ---------------- z = t + (sino - colsum)/D -----------------------------------
__global__ void k_z(const float* __restrict__ sino){
    int idx = blockIdx.x*256 + threadIdx.x;
    int j = idx & (HW-1);
    g_z[idx] = g_t[idx] + (sino[j] - g_sums[j]) * (1.f/64.f);
}

// ---------------- conv1: 1 -> 16, input derived from z, relu, -> g_h1 ---------
// tile: 4(d) x 8(h) x 32(w) outputs, all 16 co. 256 threads = (32,8).
template<int MODE>
__global__ void __launch_bounds__(256) k_conv1(const float* __restrict__ w1,
                                               const float* __restrict__ b1){
    __shared__ float sx[2040];                 // 6 x 10 x 34 halo tile
    __shared__ unsigned long long swt[216];    // 27 k x 8 co-pairs
    const int tx = threadIdx.x, ty = threadIdx.y;
    const int tid = ty*32 + tx;
    const int w0 = blockIdx.x*32, h0 = blockIdx.y*8, d0 = blockIdx.z*4;

    if (tid < 216){
        int cp = tid & 7, k = tid >> 3;
        swt[tid] = pack2(w1[(2*cp)*27 + k], w1[(2*cp+1)*27 + k]);
    }
    for (int i = tid; i < 2040; i += 256){
        int xx = i % 34; int r = i / 34;
        int yy = r % 10; int dz = r / 10;
        sx[i] = getx<MODE>(d0-1+dz, h0-1+yy, w0-1+xx);
    }
    __syncthreads();

    unsigned long long acc[4][8];
    #pragma unroll
    for (int dz=0; dz<4; dz++)
        #pragma unroll
        for (int cp=0; cp<8; cp++) acc[dz][cp] = 0ull;

    const float* bx = sx + ty*34 + tx;
    #pragma unroll
    for (int kd=0; kd<3; kd++)
    #pragma unroll
    for (int kh=0; kh<3; kh++)
    #pragma unroll
    for (int kw=0; kw<3; kw++){
        const int k = (kd*3+kh)*3+kw;
        unsigned long long x2[4];
        #pragma unroll
        for (int dz=0; dz<4; dz++){
            float xv = bx[(dz+kd)*340 + kh*34 + kw];
            x2[dz] = pack2(xv, xv);
        }
        #pragma unroll
        for (int cp=0; cp<8; cp++){
            unsigned long long wv = swt[k*8 + cp];
            #pragma unroll
            for (int dz=0; dz<4; dz++) ffma2(acc[dz][cp], x2[dz], wv);
        }
    }

    const int hh = h0+ty, ww = w0+tx;
    #pragma unroll
    for (int cp=0; cp<8; cp++){
        float bl = b1[2*cp], bh = b1[2*cp+1];
        #pragma unroll
        for (int dz=0; dz<4; dz++){
            float lo, hi; unpack2(acc[dz][cp], lo, hi);
            int idx = ((d0+dz)*Hh + hh)*Ww + ww;
            g_h1[(2*cp)*NN + idx]   = fmaxf(lo + bl, 0.f);
            g_h1[(2*cp+1)*NN + idx] = fmaxf(hi + bh, 0.f);
        }
    }
}

// ---------------- conv2: 16 -> 16, relu, g_h1 -> g_h2 (hot kernel) ------------
__global__ void __launch_bounds__(256) k_conv2(const float* __restrict__ w2,
                                               const float* __restrict__ b2){
    __shared__ float sx[4*2040];               // 4 ci x (6 x 10 x 34)
    __shared__ unsigned long long swt[4*216];  // 4 ci x 27 k x 8 co-pairs
    const int tx = threadIdx.x, ty = threadIdx.y;
    const int tid = ty*32 + tx;
    const int w0 = blockIdx.x*32, h0 = blockIdx.y*8, d0 = blockIdx.z*4;

    unsigned long long acc[4][8];
    #pragma unroll
    for (int dz=0; dz<4; dz++)
        #pragma unroll
        for (int cp=0; cp<8; cp++) acc[dz][cp] = 0ull;

    for (int cc = 0; cc < 4; cc++){
        __syncthreads();
        for (int i = tid; i < 864; i += 256){
            int cp = i & 7, k = (i >> 3) % 27, ci4 = i / 216;
            int ci = cc*4 + ci4;
            swt[i] = pack2(w2[((2*cp)*16 + ci)*27 + k],
                           w2[((2*cp+1)*16 + ci)*27 + k]);
        }
        for (int i = tid; i < 8160; i += 256){
            int xx = i % 34; int r = i / 34;
            int yy = r % 10; int r2 = r / 10;
            int dz = r2 % 6; int ci4 = r2 / 6;
            int d = d0-1+dz, h = h0-1+yy, w = w0-1+xx;
            float v = 0.f;
            if (d >= 0 && d < Dd && h >= 0 && h < Hh && w >= 0 && w < Ww)
                v = g_h1[(cc*4 + ci4)*NN + (d*Hh + h)*Ww + w];
            sx[i] = v;
        }
        __syncthreads();

        #pragma unroll 1
        for (int ci4 = 0; ci4 < 4; ci4++){
            const float* bx = sx + ci4*2040 + ty*34 + tx;
            const unsigned long long* bw = swt + ci4*216;
            #pragma unroll
            for (int kd=0; kd<3; kd++)
            #pragma unroll
            for (int kh=0; kh<3; kh++)
            #pragma unroll
            for (int kw=0; kw<3; kw++){
                const int k = (kd*3+kh)*3+kw;
                unsigned long long x2[4];
                #pragma unroll
                for (int dz=0; dz<4; dz++){
                    float xv = bx[(dz+kd)*340 + kh*34 + kw];
                    x2[dz] = pack2(xv, xv);
                }
                #pragma unroll
                for (int cp=0; cp<8; cp++){
                    unsigned long long wv = bw[k*8 + cp];
                    #pragma unroll
                    for (int dz=0; dz<4; dz++) ffma2(acc[dz][cp], x2[dz], wv);
                }
            }
        }
    }

    const int hh = h0+ty, ww = w0+tx;
    #pragma unroll
    for (int cp=0; cp<8; cp++){
        float bl = b2[2*cp], bh = b2[2*cp+1];
        #pragma unroll
        for (int dz=0; dz<4; dz++){
            float lo, hi; unpack2(acc[dz][cp], lo, hi);
            int idx = ((d0+dz)*Hh + hh)*Ww + ww;
            g_h2[(2*cp)*NN + idx]   = fmaxf(lo + bl, 0.f);
            g_h2[(2*cp+1)*NN + idx] = fmaxf(hi + bh, 0.f);
        }
    }
}

// ---------------- conv3: 16 -> 1, fused residual + p/q/s/z' update ------------
// A=0: p update (ntx), A=1: q (nty), A=2: s (ntz), A=3: z' = (1+nt)t - nt*znew
template<int A>
__global__ void __launch_bounds__(256) k_conv3(const float* __restrict__ w3,
                                               const float* __restrict__ b3,
                                               const float* __restrict__ eta_arr,
                                               int c){
    __shared__ float sx[4*2040];
    __shared__ float swt[108];                 // 4 ci x 27 k
    const int tx = threadIdx.x, ty = threadIdx.y;
    const int tid = ty*32 + tx;
    const int w0 = blockIdx.x*32, h0 = blockIdx.y*8, d0 = blockIdx.z*4;

    float acc[4] = {0.f, 0.f, 0.f, 0.f};

    for (int cc = 0; cc < 4; cc++){
        __syncthreads();
        if (tid < 108){
            int k = tid % 27, ci4 = tid / 27;
            swt[tid] = w3[(cc*4 + ci4)*27 + k];
        }
        for (int i = tid; i < 8160; i += 256){
            int xx = i % 34; int r = i / 34;
            int yy = r % 10; int r2 = r / 10;
            int dz = r2 % 6; int ci4 = r2 / 6;
            int d = d0-1+dz, h = h0-1+yy, w = w0-1+xx;
            float v = 0.f;
            if (d >= 0 && d < Dd && h >= 0 && h < Hh && w >= 0 && w < Ww)
                v = g_h2[(cc*4 + ci4)*NN + (d*Hh + h)*Ww + w];
            sx[i] = v;
        }
        __syncthreads();

        #pragma unroll 1
        for (int ci4 = 0; ci4 < 4; ci4++){
            const float* bx = sx + ci4*2040 + ty*34 + tx;
            const float* bw = swt + ci4*27;
            #pragma unroll
            for (int kd=0; kd<3; kd++)
            #pragma unroll
            for (int kh=0; kh<3; kh++)
            #pragma unroll
            for (int kw=0; kw<3; kw++){
                float wv = bw[(kd*3+kh)*3+kw];
                #pragma unroll
                for (int dz=0; dz<4; dz++)
                    acc[dz] = fmaf(bx[(dz+kd)*340 + kh*34 + kw], wv, acc[dz]);
            }
        }
    }

    float* tgt        = (A==0) ? g_p : (A==1) ? g_q : (A==2) ? g_s : g_zp;
    const float* base = (A==3) ? g_t : tgt;
    const float eta = eta_arr[c];
    const float b3v = b3[0];
    const int hh = h0+ty, ww = w0+tx;
    #pragma unroll
    for (int dz=0; dz<4; dz++){
        int d = d0+dz;
        int idx = (d*Hh + hh)*Ww + ww;
        float nnew = getx<A>(d, hh, ww) + acc[dz] + b3v;   // basic_block residual
        tgt[idx] = (1.f + eta)*base[idx] - eta*nnew;       // u + eta*(u - unew)
    }
}

// ---------------- update: t = fdT_w(p)+fdT_h(q)+fdT_d(s)+z', write out --------
__global__ void k_update(float* __restrict__ outp){
    int idx = blockIdx.x*256 + threadIdx.x;
    int w = idx & (Ww-1);
    int h = (idx >> 7) & (Hh-1);
    int d = idx >> 14;
    float fa = (w==Ww-1) ? g_p[idx-1]  : ((w>0 ? g_p[idx-1]  : 0.f) - g_p[idx]);
    float fb = (h==Hh-1) ? g_q[idx-Ww] : ((h>0 ? g_q[idx-Ww] : 0.f) - g_q[idx]);
    float fc = (d==Dd-1) ? g_s[idx-HW] : ((d>0 ? g_s[idx-HW] : 0.f) - g_s[idx]);
    float tn = fa + fb + fc + g_zp[idx];
    g_t[idx] = tn;
    outp[idx] = tn;
}

// ---------------- launcher -----------------------------------------------------
extern "C" void kernel_launch(void* const* d_in, const int* in_sizes, int n_in,
                              void* d_out, int out_size){
    (void)in_sizes; (void)n_in; (void)out_size;
    const float* img  = (const float*)d_in[0];
    const float* sino = (const float*)d_in[1];
    const float* w1   = (const float*)d_in[2];
    const float* b1   = (const float*)d_in[3];
    const float* w2   = (const float*)d_in[4];
    const float* b2   = (const float*)d_in[5];
    const float* w3   = (const float*)d_in[6];
    const float* b3   = (const float*)d_in[7];
    const float* ntx  = (const float*)d_in[8];
    const float* nty  = (const float*)d_in[9];
    const float* ntz  = (const float*)d_in[10];
    const float* nt   = (const float*)d_in[11];
    float* out = (float*)d_out;

    dim3 cg(4, 16, 16), cb(32, 8, 1);
    k_init<<<NN/256, 256>>>(img, out);
    for (int c = 0; c < 3; c++){
        k_colsum<<<HW/256, 256>>>();
        k_z<<<NN/256, 256>>>(sino);

        k_conv1<0><<<cg, cb>>>(w1 + 0*432, b1 + 0*16);
        k_conv2<<<cg, cb>>>(w2 + 0*6912, b2 + 0*16);
        k_conv3<0><<<cg, cb>>>(w3 + 0*432, b3 + 0, ntx, c);

        k_conv1<1><<<cg, cb>>>(w1 + 1*432, b1 + 1*16);
        k_conv2<<<cg, cb>>>(w2 + 1*6912, b2 + 1*16);
        k_conv3<1><<<cg, cb>>>(w3 + 1*432, b3 + 1, nty, c);

        k_conv1<2><<<cg, cb>>>(w1 + 2*432, b1 + 2*16);
        k_conv2<<<cg, cb>>>(w2 + 2*6912, b2 + 2*16);
        k_conv3<2><<<cg, cb>>>(w3 + 2*432, b3 + 2, ntz, c);

        k_conv1<3><<<cg, cb>>>(w1 + 3*432, b1 + 3*16);
        k_conv2<<<cg, cb>>>(w2 + 3*6912, b2 + 3*16);
        k_conv3<3><<<cg, cb>>>(w3 + 3*432, b3 + 3, nt, c);

        k_update<<<NN/256, 256>>>(out + (c+1)*NN);
    }
}